// round 10
// baseline (speedup 1.0000x reference)
#include <cuda_runtime.h>

#define BB   8
#define NN   128
#define COOR 3
#define FF   128
#define FILT 128

// Scratch: A' = x @ w1 + bv  and  C = x @ w2, each [B, N, COOR, FILT]
__device__ float g_A[BB * NN * COOR * FILT];
__device__ float g_C[BB * NN * COOR * FILT];

// ---- packed f32x2 helpers (phase 1 only) ----------------------------------
typedef unsigned long long ull;

union F2U {
    float2 f2;
    ull    u;
};

__device__ __forceinline__ ull fma2(ull a, ull b, ull c) {
    ull r;
    asm("fma.rn.f32x2 %0, %1, %2, %3;" : "=l"(r) : "l"(a), "l"(b), "l"(c));
    return r;
}
__device__ __forceinline__ ull pack2(float lo, float hi) {
    ull r;
    asm("mov.b64 %0, {%1, %2};" : "=l"(r) : "r"(__float_as_uint(lo)), "r"(__float_as_uint(hi)));
    return r;
}

// ---------------------------------------------------------------------------
// Phase 1 — R7 configuration VERBATIM (best measured of 5 designs: 11.4us).
// w-traffic doesn't matter (w lives in per-SM L1 within the launch); this
// config wins on warp count (20.8/SM) + DEPTH-8 register prefetch.
// ---------------------------------------------------------------------------
__global__ __launch_bounds__(128) void phase1_kernel(
    const float* __restrict__ x,   // [3072, 128]
    const float* __restrict__ w,   // [256, 128]
    const float* __restrict__ bv)  // [128]
{
    constexpr int RT    = 8;             // rows per block
    constexpr int DEPTH = 8;             // w-prefetch pipeline depth
    const int r0   = blockIdx.x * RT;
    const int kh   = blockIdx.y * 64;    // k half
    const int warp = threadIdx.x >> 5;   // 0..3
    const int lane = threadIdx.x & 31;
    const int k    = kh + lane * 2;      // this thread's k-pair
    const int wr   = warp * 2;           // first of this warp's 2 rows

    __shared__ float xs[RT][FF];         // 4 KB

    {
        const float4* xin = reinterpret_cast<const float4*>(x + (size_t)r0 * FF);
        float4* xs4 = reinterpret_cast<float4*>(&xs[0][0]);
        #pragma unroll
        for (int t = threadIdx.x; t < RT * FF / 4; t += 128) xs4[t] = xin[t];
    }
    __syncthreads();

    ull acc[2][2];   // [row][A/C]
    {
        const float2 b2 = *reinterpret_cast<const float2*>(bv + k);
        const ull bp = pack2(b2.x, b2.y);
        acc[0][0] = bp; acc[0][1] = 0ull;
        acc[1][0] = bp; acc[1][1] = 0ull;
    }

    const float* w1base = w + k;
    const float* w2base = w + (size_t)FF * FILT + k;

    F2U W1[DEPTH], W2[DEPTH];
    #pragma unroll
    for (int d = 0; d < DEPTH; d++) {
        W1[d].f2 = *reinterpret_cast<const float2*>(w1base + (size_t)d * FILT);
        W2[d].f2 = *reinterpret_cast<const float2*>(w2base + (size_t)d * FILT);
    }

    #pragma unroll 8
    for (int f = 0; f < FF; f++) {
        const int slot = f % DEPTH;

        const float xv0 = xs[wr + 0][f];
        const float xv1 = xs[wr + 1][f];
        const ull xp0 = pack2(xv0, xv0);
        const ull xp1 = pack2(xv1, xv1);

        const ull w1v = W1[slot].u;
        const ull w2v = W2[slot].u;

        acc[0][0] = fma2(xp0, w1v, acc[0][0]);
        acc[0][1] = fma2(xp0, w2v, acc[0][1]);
        acc[1][0] = fma2(xp1, w1v, acc[1][0]);
        acc[1][1] = fma2(xp1, w2v, acc[1][1]);

        if (f + DEPTH < FF) {
            W1[slot].f2 = *reinterpret_cast<const float2*>(w1base + (size_t)(f + DEPTH) * FILT);
            W2[slot].f2 = *reinterpret_cast<const float2*>(w2base + (size_t)(f + DEPTH) * FILT);
        }
    }

    #pragma unroll
    for (int r = 0; r < 2; r++) {
        const size_t row = (size_t)(r0 + wr + r);
        F2U oa; oa.u = acc[r][0];
        F2U oc; oc.u = acc[r][1];
        *reinterpret_cast<float2*>(&g_A[row * FILT + k]) = oa.f2;
        *reinterpret_cast<float2*>(&g_C[row * FILT + k]) = oc.f2;
    }
}

// ---------------------------------------------------------------------------
// Phase 2: out[b,i,j,k] = sum_c (A'[b,i,c,k] + C[b,j,c,k]) * d[b,i,j,c]
// 256 blocks (single wave), block (32,8), TI=4 i-rows, A' in registers.
// NEW: C is staged through smem in 16-j chunks with a register prefetch of
// the NEXT chunk (6 coalesced LDG.128/thread) issued BEFORE computing the
// current chunk from smem. Load->use distance = one full chunk of compute
// (~400+cyc >> 250cyc L2 latency), so warp count no longer has to hide it.
// ---------------------------------------------------------------------------
__global__ __launch_bounds__(256) void phase2_kernel(
    const float* __restrict__ dist,  // [B, N, N, COOR]
    float* __restrict__ out)         // [B, N, N, FILT]
{
    constexpr int TI = 4;
    constexpr int JC = 16;               // j-chunk size
    constexpr int NCH = NN / JC;         // 8 chunks
    constexpr int CHUNK_Q = JC * COOR * (FILT / 4);   // 1536 float4

    const int b  = blockIdx.y;
    const int i0 = blockIdx.x * TI;
    const int tx = threadIdx.x;   // 0..31
    const int ty = threadIdx.y;   // 0..7
    const int tid = ty * 32 + tx;

    __shared__ float4 sd4[TI * NN];      // padded dist (d0,d1,d2,_): 8 KB
    __shared__ float4 cs4[CHUNK_Q];      // C chunk [16j][3c][32q]: 24 KB

    // Load + pad distances slice d[b, i0:i0+4, :, :].
    {
        const float* dbase = dist + (size_t)(b * NN + i0) * NN * COOR;
        #pragma unroll
        for (int t = tid; t < TI * NN; t += 256) {
            const int e = t * COOR;
            sd4[t] = make_float4(dbase[e], dbase[e + 1], dbase[e + 2], 0.0f);
        }
    }

    // A' tile into registers: 4 i x 3 c x float4 = 48 regs.
    float4 Ar[TI][COOR];
    {
        const float4* A4 = reinterpret_cast<const float4*>(g_A);
        #pragma unroll
        for (int i = 0; i < TI; i++)
            #pragma unroll
            for (int c = 0; c < COOR; c++)
                Ar[i][c] = A4[((size_t)(b * NN + i0 + i) * COOR + c) * (FILT / 4) + tx];
    }

    const float4* Cb = reinterpret_cast<const float4*>(g_C) +
                       (size_t)b * NN * COOR * (FILT / 4);
    float4* out4 = reinterpret_cast<float4*>(out) +
                   ((size_t)(b * NN + i0) * NN) * (FILT / 4) + tx;

    // Prefetch chunk 0 into registers (6 coalesced LDG.128, MLP=6).
    float4 pf[6];
    #pragma unroll
    for (int q = 0; q < 6; q++) pf[q] = Cb[q * 256 + tid];

    __syncthreads();   // sd4 ready; cs4 untouched so far

    for (int it = 0; it < NCH; it++) {
        // Publish the prefetched chunk.
        #pragma unroll
        for (int q = 0; q < 6; q++) cs4[q * 256 + tid] = pf[q];
        __syncthreads();

        // Immediately issue next chunk's loads — covered by this chunk's compute.
        if (it + 1 < NCH) {
            const float4* src = Cb + (size_t)(it + 1) * CHUNK_Q;
            #pragma unroll
            for (int q = 0; q < 6; q++) pf[q] = src[q * 256 + tid];
        }

        // Compute this chunk: each thread handles jl = ty and ty + 8.
        #pragma unroll
        for (int h = 0; h < 2; h++) {
            const int jl = ty + h * 8;          // 0..15
            const int j  = it * JC + jl;        // global j

            const float4 c0 = cs4[(jl * COOR + 0) * (FILT / 4) + tx];  // LDS.128
            const float4 c1 = cs4[(jl * COOR + 1) * (FILT / 4) + tx];
            const float4 c2 = cs4[(jl * COOR + 2) * (FILT / 4) + tx];

            #pragma unroll
            for (int i = 0; i < TI; i++) {
                const float4 dv = sd4[i * NN + j];   // broadcast LDS.128
                const float d0 = dv.x, d1 = dv.y, d2 = dv.z;

                float4 o;
                o.x = fmaf(Ar[i][0].x + c0.x, d0,
                      fmaf(Ar[i][1].x + c1.x, d1, (Ar[i][2].x + c2.x) * d2));
                o.y = fmaf(Ar[i][0].y + c0.y, d0,
                      fmaf(Ar[i][1].y + c1.y, d1, (Ar[i][2].y + c2.y) * d2));
                o.z = fmaf(Ar[i][0].z + c0.z, d0,
                      fmaf(Ar[i][1].z + c1.z, d1, (Ar[i][2].z + c2.z) * d2));
                o.w = fmaf(Ar[i][0].w + c0.w, d0,
                      fmaf(Ar[i][1].w + c1.w, d1, (Ar[i][2].w + c2.w) * d2));

                out4[((size_t)i * NN + j) * (FILT / 4)] = o;
            }
        }
        __syncthreads();   // everyone done reading cs4 before next publish
    }
}

extern "C" void kernel_launch(void* const* d_in, const int* in_sizes, int n_in,
                              void* d_out, int out_size)
{
    const float* x    = (const float*)d_in[0];  // vector_features [8,128,3,128]
    const float* dist = (const float*)d_in[1];  // distances       [8,128,128,3]
    const float* w    = (const float*)d_in[2];  // w_vs            [256,128]
    const float* bv   = (const float*)d_in[3];  // b_vs            [128]
    float* out = (float*)d_out;                 // [8,128,128,128]

    (void)in_sizes; (void)n_in; (void)out_size;

    phase1_kernel<<<dim3((BB * NN * COOR) / 8, 2), 128>>>(x, w, bv);
    phase2_kernel<<<dim3(NN / 4, BB), dim3(32, 8)>>>(dist, out);
}